// round 4
// baseline (speedup 1.0000x reference)
#include <cuda_runtime.h>
#include <math.h>

#define NSEG 440
#define NCH  2112
#define HW   65536
#define NH   1024
#define ND   32

#define PSPLIT 16
#define TPW    (HW / PSPLIT / 32)   // 128 tiles of 32 pixels per warp

// ---------------- scratch (device globals; no allocation allowed) -------------
__device__ float g_sums[NSEG * NCH];
__device__ int   g_cnt[NSEG];
__device__ int   g_hist[NSEG * 3];
__device__ float g_feat[NSEG * NCH];
__device__ float g_fn[NSEG * NCH];
__device__ float g_h1[NSEG * NH];
__device__ float g_h2[NSEG * NH];
__device__ int   g_lab[NSEG];
__device__ float g_aff[NSEG * NSEG];

// ---------------- zero scratch (must run every replay) ------------------------
__global__ void k_zero() {
    int i = blockIdx.x * blockDim.x + threadIdx.x;
    if (i < NSEG * NCH) g_sums[i] = 0.f;
    if (i < NSEG)       g_cnt[i]  = 0;
    if (i < NSEG * 3)   g_hist[i] = 0;
}

// ---------------- per-segment pixel counts + class histogram ------------------
__global__ void k_hist(const int* __restrict__ sp, const int* __restrict__ y) {
    int p = blockIdx.x * blockDim.x + threadIdx.x;
    if (p < HW) {
        int s = sp[p];
        atomicAdd(&g_cnt[s], 1);
        atomicAdd(&g_hist[s * 3 + y[p]], 1);
    }
}

// ---------------- segment feature sums: conflict-free smem privatization ------
// 1 warp/block. Block = 32 channels x (HW/PSPLIT) pixels.
// acc[seg][lane] : lane l exclusively owns channel c0+l  -> bank l, no conflicts,
// no atomics. 32x32 tile register->smem staging gives both coalesced gmem loads
// and lane-owns-channel accumulation. Flush via scalar REDG (14.9M elems total).
__global__ __launch_bounds__(32) void k_seg(const float* __restrict__ fm,
                                            const int* __restrict__ sp) {
    extern __shared__ float sh[];
    float* acc   = sh;                 // [NSEG][32]
    float* stage = sh + NSEG * 32;     // [32][33]
    const int l  = threadIdx.x;
    const int c0 = blockIdx.x * 32;
    const int pbase = blockIdx.y * (HW / PSPLIT);
    const float* fb = fm + (size_t)c0 * HW;

    for (int i = l; i < NSEG * 32; i += 32) acc[i] = 0.f;
    __syncwarp();

    float ra[32], rb[32];
    int sa = 0, sb = 0;

    {   // preload tile 0
        int p = pbase + l;
#pragma unroll
        for (int i = 0; i < 32; ++i) ra[i] = __ldg(&fb[(size_t)i * HW + p]);
        sa = __ldg(&sp[p]);
    }

#define PROCESS(cur, scur)                                             \
    {                                                                  \
        __syncwarp();                                                  \
        _Pragma("unroll")                                              \
        for (int i = 0; i < 32; ++i) stage[i * 33 + l] = cur[i];       \
        __syncwarp();                                                  \
        _Pragma("unroll")                                              \
        for (int i = 0; i < 32; ++i) {                                 \
            int s = __shfl_sync(0xffffffffu, scur, i);                 \
            acc[s * 32 + l] += stage[l * 33 + i];                      \
        }                                                              \
    }

    for (int t = 0; t < TPW; t += 2) {
        {   // prefetch tile t+1 (TPW even -> always valid)
            int p = pbase + (t + 1) * 32 + l;
#pragma unroll
            for (int i = 0; i < 32; ++i) rb[i] = __ldg(&fb[(size_t)i * HW + p]);
            sb = __ldg(&sp[p]);
        }
        PROCESS(ra, sa);
        if (t + 2 < TPW) {   // prefetch tile t+2
            int p = pbase + (t + 2) * 32 + l;
#pragma unroll
            for (int i = 0; i < 32; ++i) ra[i] = __ldg(&fb[(size_t)i * HW + p]);
            sa = __ldg(&sp[p]);
        }
        PROCESS(rb, sb);
    }
#undef PROCESS

    __syncwarp();
    for (int s = 0; s < NSEG; ++s) {
        float v = acc[s * 32 + l];
        float* dst = &g_sums[(size_t)s * NCH + c0 + l];
        asm volatile("red.global.add.f32 [%0], %1;" :: "l"(dst), "f"(v) : "memory");
    }
}

// ---------------- labels from histogram (exact int replication of reference) --
__global__ void k_lab() {
    int s = blockIdx.x * blockDim.x + threadIdx.x;
    if (s < NSEG) {
        int h0 = g_hist[s * 3 + 0];
        int h1 = g_hist[s * 3 + 1];
        int h2 = g_hist[s * 3 + 2];
        int l = 0, best = h0;
        if (h1 > best) { best = h1; l = 1; }
        if (h2 > best) { best = h2; l = 2; }
        if (l == 0) l = (h2 > h1) ? 2 : ((h1 > h2) ? 1 : 0);
        g_lab[s] = l;
    }
}

// ---------------- feat = sums/max(cnt,1); fn = feat/||feat|| -------------------
__global__ __launch_bounds__(256) void k_feat() {
    int s = blockIdx.x;
    int t = threadIdx.x;
    float cnt = (float)g_cnt[s];
    if (cnt < 1.f) cnt = 1.f;
    float sq = 0.f;
    for (int c = t; c < NCH; c += 256) {
        float v = g_sums[(size_t)s * NCH + c] / cnt;
        g_feat[(size_t)s * NCH + c] = v;
        sq += v * v;
    }
    __shared__ float red[256];
    red[t] = sq;
    __syncthreads();
    for (int o = 128; o; o >>= 1) {
        if (t < o) red[t] += red[t + o];
        __syncthreads();
    }
    float nrm = sqrtf(red[0]);
    for (int c = t; c < NCH; c += 256) {
        g_fn[(size_t)s * NCH + c] = g_feat[(size_t)s * NCH + c] / nrm;
    }
}

// ---------------- fp32 GEMM: C = relu(A @ B + bias), A:MxK, B:KxN row-major ----
__global__ __launch_bounds__(256) void k_gemm_relu(
    const float* __restrict__ A, const float* __restrict__ B,
    const float* __restrict__ bias, float* __restrict__ Cout,
    int M, int N, int K)
{
    __shared__ float As[16][64];
    __shared__ float Bs[16][64];
    int tx = threadIdx.x, ty = threadIdx.y;
    int tid = ty * 16 + tx;
    int row0 = blockIdx.y * 64;
    int col0 = blockIdx.x * 64;

    float acc[4][4] = {};

    int aRow = tid >> 2;
    int aCol = (tid & 3) * 4;
    int bRow = tid >> 4;
    int bCol = (tid & 15) * 4;

    for (int k0 = 0; k0 < K; k0 += 16) {
        float4 av;
        int gm = row0 + aRow;
        if (gm < M) av = *(const float4*)&A[(size_t)gm * K + k0 + aCol];
        else        av = make_float4(0.f, 0.f, 0.f, 0.f);
        As[aCol + 0][aRow] = av.x;
        As[aCol + 1][aRow] = av.y;
        As[aCol + 2][aRow] = av.z;
        As[aCol + 3][aRow] = av.w;

        float4 bv = *(const float4*)&B[(size_t)(k0 + bRow) * N + col0 + bCol];
        *(float4*)&Bs[bRow][bCol] = bv;
        __syncthreads();

#pragma unroll
        for (int kk = 0; kk < 16; ++kk) {
            float4 a = *(float4*)&As[kk][ty * 4];
            float4 b = *(float4*)&Bs[kk][tx * 4];
            float aa[4] = {a.x, a.y, a.z, a.w};
            float bb[4] = {b.x, b.y, b.z, b.w};
#pragma unroll
            for (int i = 0; i < 4; ++i)
#pragma unroll
                for (int j = 0; j < 4; ++j)
                    acc[i][j] += aa[i] * bb[j];
        }
        __syncthreads();
    }

#pragma unroll
    for (int i = 0; i < 4; ++i) {
        int m = row0 + ty * 4 + i;
        if (m < M) {
#pragma unroll
            for (int j = 0; j < 4; ++j) {
                int n = col0 + tx * 4 + j;
                float v = acc[i][j] + bias[n];
                Cout[(size_t)m * N + n] = fmaxf(v, 0.f);
            }
        }
    }
}

// ---------------- affinity: aff[i][j] = expf(-dot(fn_i, fn_j)) -----------------
__global__ __launch_bounds__(256) void k_aff() {
    __shared__ float As[16][64];
    __shared__ float Bs[16][64];
    int tx = threadIdx.x, ty = threadIdx.y;
    int tid = ty * 16 + tx;
    int i0 = blockIdx.y * 64;
    int j0 = blockIdx.x * 64;

    float acc[4][4] = {};

    int aRow = tid >> 2;
    int aCol = (tid & 3) * 4;

    for (int k0 = 0; k0 < NCH; k0 += 16) {
        int gi = i0 + aRow;
        int gj = j0 + aRow;
        float4 av = (gi < NSEG) ? *(const float4*)&g_fn[(size_t)gi * NCH + k0 + aCol]
                                : make_float4(0.f, 0.f, 0.f, 0.f);
        float4 bv = (gj < NSEG) ? *(const float4*)&g_fn[(size_t)gj * NCH + k0 + aCol]
                                : make_float4(0.f, 0.f, 0.f, 0.f);
        As[aCol + 0][aRow] = av.x; As[aCol + 1][aRow] = av.y;
        As[aCol + 2][aRow] = av.z; As[aCol + 3][aRow] = av.w;
        Bs[aCol + 0][aRow] = bv.x; Bs[aCol + 1][aRow] = bv.y;
        Bs[aCol + 2][aRow] = bv.z; Bs[aCol + 3][aRow] = bv.w;
        __syncthreads();

#pragma unroll
        for (int kk = 0; kk < 16; ++kk) {
            float4 a = *(float4*)&As[kk][ty * 4];
            float4 b = *(float4*)&Bs[kk][tx * 4];
            float aa[4] = {a.x, a.y, a.z, a.w};
            float bb[4] = {b.x, b.y, b.z, b.w};
#pragma unroll
            for (int i = 0; i < 4; ++i)
#pragma unroll
                for (int j = 0; j < 4; ++j)
                    acc[i][j] += aa[i] * bb[j];
        }
        __syncthreads();
    }

#pragma unroll
    for (int i = 0; i < 4; ++i) {
        int gi = i0 + ty * 4 + i;
        if (gi < NSEG) {
#pragma unroll
            for (int j = 0; j < 4; ++j) {
                int gj = j0 + tx * 4 + j;
                if (gj < NSEG)
                    g_aff[gi * NSEG + gj] = expf(-acc[i][j]);
            }
        }
    }
}

// ---------------- MLP tail: h3 = relu(h2@W3+b3); pred = softmax(h3@Wc+bc) -----
__global__ __launch_bounds__(256) void k_head(const float* __restrict__ W3,
                                              const float* __restrict__ b3,
                                              const float* __restrict__ Wc,
                                              const float* __restrict__ bc,
                                              float* __restrict__ out) {
    int r = blockIdx.x;
    int t = threadIdx.x;
    int n = t & 31;
    int ks = t >> 5;
    const float* h2r = g_h2 + (size_t)r * NH;

    float acc = 0.f;
    for (int kk = 0; kk < 128; ++kk) {
        int k = ks * 128 + kk;
        acc += h2r[k] * W3[k * 32 + n];
    }
    __shared__ float red[256];
    __shared__ float h3[32];
    red[t] = acc;
    __syncthreads();
    if (t < 32) {
        float v = red[t];
#pragma unroll
        for (int q = 1; q < 8; ++q) v += red[q * 32 + t];
        v += b3[t];
        h3[t] = fmaxf(v, 0.f);
    }
    __syncthreads();
    if (t == 0) {
        float l0 = bc[0], l1 = bc[1];
#pragma unroll
        for (int d = 0; d < 32; ++d) {
            l0 += h3[d] * Wc[d * 2 + 0];
            l1 += h3[d] * Wc[d * 2 + 1];
        }
        float m = fmaxf(l0, l1);
        float e0 = expf(l0 - m), e1 = expf(l1 - m);
        float inv = 1.f / (e0 + e1);
        out[r * 2 + 0] = e0 * inv;
        out[r * 2 + 1] = e1 * inv;
    }
}

// ---------------- label propagation: masked argmax over aff row ---------------
__global__ __launch_bounds__(128) void k_prop(float* __restrict__ out) {
    int i = blockIdx.x;
    int t = threadIdx.x;
    float bv = -INFINITY;
    int   bi = 0;
    for (int j = t; j < NSEG; j += 128) {
        if (g_lab[j] != 0) {
            float v = g_aff[i * NSEG + j];
            if (v > bv) { bv = v; bi = j; }
        }
    }
    __shared__ float sv[128];
    __shared__ int   si[128];
    sv[t] = bv; si[t] = bi;
    __syncthreads();
    for (int o = 64; o; o >>= 1) {
        if (t < o) {
            float v2 = sv[t + o]; int i2 = si[t + o];
            if (v2 > sv[t] || (v2 == sv[t] && i2 < si[t])) { sv[t] = v2; si[t] = i2; }
        }
        __syncthreads();
    }
    if (t == 0) {
        int li = g_lab[i];
        int nl = (li == 0 && sv[0] >= 0.7f) ? g_lab[si[0]] : li;
        out[880 + i] = (float)nl;
    }
}

// ---------------- launcher -----------------------------------------------------
extern "C" void kernel_launch(void* const* d_in, const int* in_sizes, int n_in,
                              void* d_out, int out_size) {
    const float* fm = (const float*)d_in[0];
    const int*   sp = (const int*)d_in[1];
    const int*   y  = (const int*)d_in[2];
    const float* W1 = (const float*)d_in[3];
    const float* b1 = (const float*)d_in[4];
    const float* W2 = (const float*)d_in[5];
    const float* b2 = (const float*)d_in[6];
    const float* W3 = (const float*)d_in[7];
    const float* b3 = (const float*)d_in[8];
    const float* Wc = (const float*)d_in[9];
    const float* bc = (const float*)d_in[10];
    float* out = (float*)d_out;

    void *p_feat, *p_h1, *p_h2;
    cudaGetSymbolAddress(&p_feat, g_feat);
    cudaGetSymbolAddress(&p_h1, g_h1);
    cudaGetSymbolAddress(&p_h2, g_h2);

    const int SEG_SMEM = (NSEG * 32 + 32 * 33) * sizeof(float);   // 60544 B
    static int configured = 0;
    if (!configured) {
        cudaFuncSetAttribute(k_seg, cudaFuncAttributeMaxDynamicSharedMemorySize, SEG_SMEM);
        configured = 1;
    }

    k_zero<<<(NSEG * NCH + 255) / 256, 256>>>();
    k_hist<<<HW / 256, 256>>>(sp, y);
    k_seg<<<dim3(NCH / 32, PSPLIT), 32, SEG_SMEM>>>(fm, sp);
    k_lab<<<2, 256>>>();
    k_feat<<<NSEG, 256>>>();

    // h1 = relu(feat @ W1 + b1) : (440 x 2112) @ (2112 x 1024)
    k_gemm_relu<<<dim3(NH / 64, (NSEG + 63) / 64), dim3(16, 16)>>>(
        (const float*)p_feat, W1, b1, (float*)p_h1, NSEG, NH, NCH);
    // h2 = relu(h1 @ W2 + b2) : (440 x 1024) @ (1024 x 1024)
    k_gemm_relu<<<dim3(NH / 64, (NSEG + 63) / 64), dim3(16, 16)>>>(
        (const float*)p_h1, W2, b2, (float*)p_h2, NSEG, NH, NH);

    k_head<<<NSEG, 256>>>(W3, b3, Wc, bc, out);
    k_aff<<<dim3((NSEG + 63) / 64, (NSEG + 63) / 64), dim3(16, 16)>>>();
    k_prop<<<NSEG, 128>>>(out);
}

// round 6
// speedup vs baseline: 1.1653x; 1.1653x over previous
#include <cuda_runtime.h>
#include <math.h>

#define NSEG 440
#define NCH  2112
#define HW   65536
#define NH   1024
#define ND   32

// channel split between the two pooling engines
#define CH_R 1152              // channels 0..1151    -> L2 REDG path
#define CH_S (NCH - CH_R)      // channels 1152..2111 -> smem-atomic path

// ---------------- scratch (device globals; no allocation allowed) -------------
__device__ float g_sums[NSEG * NCH];
__device__ int   g_cnt[NSEG];
__device__ int   g_hist[NSEG * 3];
__device__ float g_feat[NSEG * NCH];
__device__ float g_fn[NSEG * NCH];
__device__ float g_h1[NSEG * NH];
__device__ float g_h2[NSEG * NH];
__device__ int   g_lab[NSEG];
__device__ float g_aff[NSEG * NSEG];

// ---------------- zero scratch (must run every replay) ------------------------
__global__ void k_zero() {
    int i = blockIdx.x * blockDim.x + threadIdx.x;
    if (i < NSEG * NCH) g_sums[i] = 0.f;
    if (i < NSEG)       g_cnt[i]  = 0;
    if (i < NSEG * 3)   g_hist[i] = 0;
}

// ---------------- per-segment pixel counts + class histogram ------------------
__global__ void k_hist(const int* __restrict__ sp, const int* __restrict__ y) {
    int p = blockIdx.x * blockDim.x + threadIdx.x;
    if (p < HW) {
        int s = sp[p];
        atomicAdd(&g_cnt[s], 1);
        atomicAdd(&g_hist[s * 3 + y[p]], 1);
    }
}

// ---------------- hybrid segment pooling ---------------------------------------
// Two engines in ONE kernel (so they overlap in time):
//  role SMEM: 480 blocks  = 120 ch-groups(8ch) x 4 pixel-splits; smem atomicAdd
//             privatization (SM ATOMS units), REDG flush at end (1.7M elems).
//  role REDG: 2304 blocks = 288 ch-groups(4ch) x 8 pixel-splits; direct
//             red.global.add.v4.f32 (LTS atomic ALUs).
// Interleave: groups of 29 blocks = 5 SMEM + 24 REDG (2784 = 29*96).
__global__ __launch_bounds__(256) void k_seg(const float* __restrict__ fm,
                                             const int* __restrict__ sp) {
    __shared__ float ss[8 * NSEG];
    int bid = blockIdx.x;
    int grp = bid / 29, rem = bid % 29;
    int tid = threadIdx.x;

    if (rem < 5) {
        // ---- SMEM role ----
        int i  = grp * 5 + rem;          // 0..479
        int cg = i % 120, ps = i / 120;  // 120 groups, 4 pixel splits
        int c0 = CH_R + cg * 8;
        int base = ps * 16384;
        const float* f0 = fm + (size_t)c0 * HW;

        for (int k = tid; k < 8 * NSEG; k += 256) ss[k] = 0.f;
        __syncthreads();

        for (int it = 0; it < 64; ++it) {
            int p = base + it * 256 + tid;
            int s = __ldg(&sp[p]);
#pragma unroll
            for (int j = 0; j < 8; ++j)
                atomicAdd(&ss[j * NSEG + s], __ldg(&f0[(size_t)j * HW + p]));
        }
        __syncthreads();

        for (int k = tid; k < 8 * NSEG; k += 256) {
            int j = k / NSEG;
            int s = k - j * NSEG;
            float* dst = &g_sums[(size_t)s * NCH + c0 + j];
            asm volatile("red.global.add.f32 [%0], %1;"
                         :: "l"(dst), "f"(ss[k]) : "memory");
        }
    } else {
        // ---- REDG role ----
        int j  = grp * 24 + (rem - 5);   // 0..2303
        int cg = j % 288, ps = j / 288;  // 288 groups, 8 pixel splits
        int c0 = cg * 4;
        int base = ps * 8192;
        const float* f0 = fm + (size_t)c0 * HW;

#pragma unroll 4
        for (int it = 0; it < 32; ++it) {
            int p = base + it * 256 + tid;
            int s = __ldg(&sp[p]);
            float a = __ldg(&f0[p]);
            float b = __ldg(&f0[HW + p]);
            float c = __ldg(&f0[2 * HW + p]);
            float d = __ldg(&f0[3 * HW + p]);
            float* dst = &g_sums[(size_t)s * NCH + c0];
            asm volatile("red.global.add.v4.f32 [%0], {%1,%2,%3,%4};"
                         :: "l"(dst), "f"(a), "f"(b), "f"(c), "f"(d)
                         : "memory");
        }
    }
}

// ---------------- labels from histogram (exact int replication of reference) --
__global__ void k_lab() {
    int s = blockIdx.x * blockDim.x + threadIdx.x;
    if (s < NSEG) {
        int h0 = g_hist[s * 3 + 0];
        int h1 = g_hist[s * 3 + 1];
        int h2 = g_hist[s * 3 + 2];
        int l = 0, best = h0;
        if (h1 > best) { best = h1; l = 1; }
        if (h2 > best) { best = h2; l = 2; }
        if (l == 0) l = (h2 > h1) ? 2 : ((h1 > h2) ? 1 : 0);
        g_lab[s] = l;
    }
}

// ---------------- feat = sums/max(cnt,1); fn = feat/||feat|| -------------------
__global__ __launch_bounds__(256) void k_feat() {
    int s = blockIdx.x;
    int t = threadIdx.x;
    float cnt = (float)g_cnt[s];
    if (cnt < 1.f) cnt = 1.f;
    float sq = 0.f;
    for (int c = t; c < NCH; c += 256) {
        float v = g_sums[(size_t)s * NCH + c] / cnt;
        g_feat[(size_t)s * NCH + c] = v;
        sq += v * v;
    }
    __shared__ float red[256];
    red[t] = sq;
    __syncthreads();
    for (int o = 128; o; o >>= 1) {
        if (t < o) red[t] += red[t + o];
        __syncthreads();
    }
    float nrm = sqrtf(red[0]);
    for (int c = t; c < NCH; c += 256) {
        g_fn[(size_t)s * NCH + c] = g_feat[(size_t)s * NCH + c] / nrm;
    }
}

// ---------------- fp32 GEMM: C = relu(A @ B + bias), A:MxK, B:KxN row-major ----
__global__ __launch_bounds__(256) void k_gemm_relu(
    const float* __restrict__ A, const float* __restrict__ B,
    const float* __restrict__ bias, float* __restrict__ Cout,
    int M, int N, int K)
{
    __shared__ float As[16][64];
    __shared__ float Bs[16][64];
    int tx = threadIdx.x, ty = threadIdx.y;
    int tid = ty * 16 + tx;
    int row0 = blockIdx.y * 64;
    int col0 = blockIdx.x * 64;

    float acc[4][4] = {};

    int aRow = tid >> 2;
    int aCol = (tid & 3) * 4;
    int bRow = tid >> 4;
    int bCol = (tid & 15) * 4;

    for (int k0 = 0; k0 < K; k0 += 16) {
        float4 av;
        int gm = row0 + aRow;
        if (gm < M) av = *(const float4*)&A[(size_t)gm * K + k0 + aCol];
        else        av = make_float4(0.f, 0.f, 0.f, 0.f);
        As[aCol + 0][aRow] = av.x;
        As[aCol + 1][aRow] = av.y;
        As[aCol + 2][aRow] = av.z;
        As[aCol + 3][aRow] = av.w;

        float4 bv = *(const float4*)&B[(size_t)(k0 + bRow) * N + col0 + bCol];
        *(float4*)&Bs[bRow][bCol] = bv;
        __syncthreads();

#pragma unroll
        for (int kk = 0; kk < 16; ++kk) {
            float4 a = *(float4*)&As[kk][ty * 4];
            float4 b = *(float4*)&Bs[kk][tx * 4];
            float aa[4] = {a.x, a.y, a.z, a.w};
            float bb[4] = {b.x, b.y, b.z, b.w};
#pragma unroll
            for (int i = 0; i < 4; ++i)
#pragma unroll
                for (int j = 0; j < 4; ++j)
                    acc[i][j] += aa[i] * bb[j];
        }
        __syncthreads();
    }

#pragma unroll
    for (int i = 0; i < 4; ++i) {
        int m = row0 + ty * 4 + i;
        if (m < M) {
#pragma unroll
            for (int j = 0; j < 4; ++j) {
                int n = col0 + tx * 4 + j;
                float v = acc[i][j] + bias[n];
                Cout[(size_t)m * N + n] = fmaxf(v, 0.f);
            }
        }
    }
}

// ---------------- affinity: aff[i][j] = expf(-dot(fn_i, fn_j)) -----------------
__global__ __launch_bounds__(256) void k_aff() {
    __shared__ float As[16][64];
    __shared__ float Bs[16][64];
    int tx = threadIdx.x, ty = threadIdx.y;
    int tid = ty * 16 + tx;
    int i0 = blockIdx.y * 64;
    int j0 = blockIdx.x * 64;

    float acc[4][4] = {};

    int aRow = tid >> 2;
    int aCol = (tid & 3) * 4;

    for (int k0 = 0; k0 < NCH; k0 += 16) {
        int gi = i0 + aRow;
        int gj = j0 + aRow;
        float4 av = (gi < NSEG) ? *(const float4*)&g_fn[(size_t)gi * NCH + k0 + aCol]
                                : make_float4(0.f, 0.f, 0.f, 0.f);
        float4 bv = (gj < NSEG) ? *(const float4*)&g_fn[(size_t)gj * NCH + k0 + aCol]
                                : make_float4(0.f, 0.f, 0.f, 0.f);
        As[aCol + 0][aRow] = av.x; As[aCol + 1][aRow] = av.y;
        As[aCol + 2][aRow] = av.z; As[aCol + 3][aRow] = av.w;
        Bs[aCol + 0][aRow] = bv.x; Bs[aCol + 1][aRow] = bv.y;
        Bs[aCol + 2][aRow] = bv.z; Bs[aCol + 3][aRow] = bv.w;
        __syncthreads();

#pragma unroll
        for (int kk = 0; kk < 16; ++kk) {
            float4 a = *(float4*)&As[kk][ty * 4];
            float4 b = *(float4*)&Bs[kk][tx * 4];
            float aa[4] = {a.x, a.y, a.z, a.w};
            float bb[4] = {b.x, b.y, b.z, b.w};
#pragma unroll
            for (int i = 0; i < 4; ++i)
#pragma unroll
                for (int j = 0; j < 4; ++j)
                    acc[i][j] += aa[i] * bb[j];
        }
        __syncthreads();
    }

#pragma unroll
    for (int i = 0; i < 4; ++i) {
        int gi = i0 + ty * 4 + i;
        if (gi < NSEG) {
#pragma unroll
            for (int j = 0; j < 4; ++j) {
                int gj = j0 + tx * 4 + j;
                if (gj < NSEG)
                    g_aff[gi * NSEG + gj] = expf(-acc[i][j]);
            }
        }
    }
}

// ---------------- MLP tail: h3 = relu(h2@W3+b3); pred = softmax(h3@Wc+bc) -----
__global__ __launch_bounds__(256) void k_head(const float* __restrict__ W3,
                                              const float* __restrict__ b3,
                                              const float* __restrict__ Wc,
                                              const float* __restrict__ bc,
                                              float* __restrict__ out) {
    int r = blockIdx.x;
    int t = threadIdx.x;
    int n = t & 31;
    int ks = t >> 5;
    const float* h2r = g_h2 + (size_t)r * NH;

    float acc = 0.f;
    for (int kk = 0; kk < 128; ++kk) {
        int k = ks * 128 + kk;
        acc += h2r[k] * W3[k * 32 + n];
    }
    __shared__ float red[256];
    __shared__ float h3[32];
    red[t] = acc;
    __syncthreads();
    if (t < 32) {
        float v = red[t];
#pragma unroll
        for (int q = 1; q < 8; ++q) v += red[q * 32 + t];
        v += b3[t];
        h3[t] = fmaxf(v, 0.f);
    }
    __syncthreads();
    if (t == 0) {
        float l0 = bc[0], l1 = bc[1];
#pragma unroll
        for (int d = 0; d < 32; ++d) {
            l0 += h3[d] * Wc[d * 2 + 0];
            l1 += h3[d] * Wc[d * 2 + 1];
        }
        float m = fmaxf(l0, l1);
        float e0 = expf(l0 - m), e1 = expf(l1 - m);
        float inv = 1.f / (e0 + e1);
        out[r * 2 + 0] = e0 * inv;
        out[r * 2 + 1] = e1 * inv;
    }
}

// ---------------- label propagation: masked argmax over aff row ---------------
__global__ __launch_bounds__(128) void k_prop(float* __restrict__ out) {
    int i = blockIdx.x;
    int t = threadIdx.x;
    float bv = -INFINITY;
    int   bi = 0;
    for (int j = t; j < NSEG; j += 128) {
        if (g_lab[j] != 0) {
            float v = g_aff[i * NSEG + j];
            if (v > bv) { bv = v; bi = j; }
        }
    }
    __shared__ float sv[128];
    __shared__ int   si[128];
    sv[t] = bv; si[t] = bi;
    __syncthreads();
    for (int o = 64; o; o >>= 1) {
        if (t < o) {
            float v2 = sv[t + o]; int i2 = si[t + o];
            if (v2 > sv[t] || (v2 == sv[t] && i2 < si[t])) { sv[t] = v2; si[t] = i2; }
        }
        __syncthreads();
    }
    if (t == 0) {
        int li = g_lab[i];
        int nl = (li == 0 && sv[0] >= 0.7f) ? g_lab[si[0]] : li;
        out[880 + i] = (float)nl;
    }
}

// ---------------- launcher -----------------------------------------------------
extern "C" void kernel_launch(void* const* d_in, const int* in_sizes, int n_in,
                              void* d_out, int out_size) {
    const float* fm = (const float*)d_in[0];
    const int*   sp = (const int*)d_in[1];
    const int*   y  = (const int*)d_in[2];
    const float* W1 = (const float*)d_in[3];
    const float* b1 = (const float*)d_in[4];
    const float* W2 = (const float*)d_in[5];
    const float* b2 = (const float*)d_in[6];
    const float* W3 = (const float*)d_in[7];
    const float* b3 = (const float*)d_in[8];
    const float* Wc = (const float*)d_in[9];
    const float* bc = (const float*)d_in[10];
    float* out = (float*)d_out;

    void *p_feat, *p_h1, *p_h2;
    cudaGetSymbolAddress(&p_feat, g_feat);
    cudaGetSymbolAddress(&p_h1, g_h1);
    cudaGetSymbolAddress(&p_h2, g_h2);

    k_zero<<<(NSEG * NCH + 255) / 256, 256>>>();
    k_hist<<<HW / 256, 256>>>(sp, y);
    k_seg<<<29 * 96, 256>>>(fm, sp);   // 480 SMEM-role + 2304 REDG-role blocks
    k_lab<<<2, 256>>>();
    k_feat<<<NSEG, 256>>>();

    // h1 = relu(feat @ W1 + b1) : (440 x 2112) @ (2112 x 1024)
    k_gemm_relu<<<dim3(NH / 64, (NSEG + 63) / 64), dim3(16, 16)>>>(
        (const float*)p_feat, W1, b1, (float*)p_h1, NSEG, NH, NCH);
    // h2 = relu(h1 @ W2 + b2) : (440 x 1024) @ (1024 x 1024)
    k_gemm_relu<<<dim3(NH / 64, (NSEG + 63) / 64), dim3(16, 16)>>>(
        (const float*)p_h1, W2, b2, (float*)p_h2, NSEG, NH, NH);

    k_head<<<NSEG, 256>>>(W3, b3, Wc, bc, out);
    k_aff<<<dim3((NSEG + 63) / 64, (NSEG + 63) / 64), dim3(16, 16)>>>();
    k_prop<<<NSEG, 128>>>(out);
}

// round 15
// speedup vs baseline: 1.6630x; 1.4271x over previous
#include <cuda_runtime.h>
#include <math.h>

#define NSEG 440
#define NCH  2112
#define HW   65536
#define NH   1024

// ---------------- scratch (device globals; no allocation allowed) -------------
__device__ float g_sums[NSEG * NCH];
__device__ int   g_cnt[NSEG];
__device__ int   g_hist[NSEG * 3];
__device__ float g_feat[NSEG * NCH];
__device__ float g_fn[NSEG * NCH];
__device__ float g_h1[NSEG * NH];
__device__ float g_h2[NSEG * NH];
__device__ int   g_lab[NSEG];
__device__ float g_aff[NSEG * NSEG];   // holds raw dot(fn_i, fn_j) (split-K REDG)

// ---------------- packed f32x2 helpers ----------------------------------------
#define PACK2(out, lo, hi) \
    asm("mov.b64 %0, {%1, %2};" : "=l"(out) : "f"(lo), "f"(hi))
#define UNPACK2(lo, hi, in) \
    asm("mov.b64 {%0, %1}, %2;" : "=f"(lo), "=f"(hi) : "l"(in))
#define FMA2(c, a, b) \
    asm("fma.rn.f32x2 %0, %1, %2, %0;" : "+l"(c) : "l"(a), "l"(b))

// ---------------- zero scratch (must run every replay) ------------------------
__global__ void k_zero() {
    int i = blockIdx.x * blockDim.x + threadIdx.x;
    if (i < NSEG * NCH)  g_sums[i] = 0.f;
    if (i < NSEG)        g_cnt[i]  = 0;
    if (i < NSEG * 3)    g_hist[i] = 0;
    if (i < NSEG * NSEG) g_aff[i]  = 0.f;
}

// ---------------- per-segment pixel counts + class histogram ------------------
__global__ void k_hist(const int* __restrict__ sp, const int* __restrict__ y) {
    int p = blockIdx.x * blockDim.x + threadIdx.x;
    if (p < HW) {
        int s = sp[p];
        atomicAdd(&g_cnt[s], 1);
        atomicAdd(&g_hist[s * 3 + y[p]], 1);
    }
}

// ---------------- segment feature sums (R2 proven REDG-v4 path) ----------------
__global__ __launch_bounds__(256) void k_seg(const float* __restrict__ fm,
                                             const int* __restrict__ sp) {
    int c0   = blockIdx.x * 4;
    int base = blockIdx.y * 8192;
    int t    = threadIdx.x;
    const float* f0 = fm + (size_t)c0 * HW;

#pragma unroll 4
    for (int it = 0; it < 32; ++it) {
        int p = base + it * 256 + t;
        int s = __ldg(&sp[p]);
        float a = __ldg(&f0[p]);
        float b = __ldg(&f0[HW + p]);
        float c = __ldg(&f0[2 * HW + p]);
        float d = __ldg(&f0[3 * HW + p]);
        float* dst = &g_sums[(size_t)s * NCH + c0];
        asm volatile("red.global.add.v4.f32 [%0], {%1,%2,%3,%4};"
                     :: "l"(dst), "f"(a), "f"(b), "f"(c), "f"(d)
                     : "memory");
    }
}

// ---------------- feat = sums/max(cnt,1); fn = feat/||feat||; + label ----------
__global__ __launch_bounds__(256) void k_feat() {
    int s = blockIdx.x;
    int t = threadIdx.x;

    if (t == 0) {   // fused k_lab (exact int replication of reference)
        int h0 = g_hist[s * 3 + 0];
        int h1 = g_hist[s * 3 + 1];
        int h2 = g_hist[s * 3 + 2];
        int l = 0, best = h0;
        if (h1 > best) { best = h1; l = 1; }
        if (h2 > best) { best = h2; l = 2; }
        if (l == 0) l = (h2 > h1) ? 2 : ((h1 > h2) ? 1 : 0);
        g_lab[s] = l;
    }

    float cnt = (float)g_cnt[s];
    if (cnt < 1.f) cnt = 1.f;
    float sq = 0.f;
    for (int c = t; c < NCH; c += 256) {
        float v = g_sums[(size_t)s * NCH + c] / cnt;
        g_feat[(size_t)s * NCH + c] = v;
        sq += v * v;
    }
    __shared__ float red[256];
    red[t] = sq;
    __syncthreads();
    for (int o = 128; o; o >>= 1) {
        if (t < o) red[t] += red[t + o];
        __syncthreads();
    }
    float nrm = sqrtf(red[0]);
    for (int c = t; c < NCH; c += 256) {
        g_fn[(size_t)s * NCH + c] = g_feat[(size_t)s * NCH + c] / nrm;
    }
}

// ---------------- f32x2 GEMM: C = relu(A @ B + bias) ---------------------------
// block 16x16 threads, 64x64 tile, 4x4 per thread (as 4 x 2 f32x2 pairs), BK=16.
__global__ __launch_bounds__(256) void k_gemm_relu(
    const float* __restrict__ A, const float* __restrict__ B,
    const float* __restrict__ bias, float* __restrict__ Cout,
    int M, int N, int K)
{
    __shared__ float As[16][64];
    __shared__ float Bs[16][64];
    int tx = threadIdx.x, ty = threadIdx.y;
    int tid = ty * 16 + tx;
    int row0 = blockIdx.y * 64;
    int col0 = blockIdx.x * 64;

    unsigned long long acc2[4][2];
#pragma unroll
    for (int i = 0; i < 4; ++i) { acc2[i][0] = 0ull; acc2[i][1] = 0ull; }

    int aRow = tid >> 2;
    int aCol = (tid & 3) * 4;
    int bRow = tid >> 4;
    int bCol = (tid & 15) * 4;

    for (int k0 = 0; k0 < K; k0 += 16) {
        float4 av;
        int gm = row0 + aRow;
        if (gm < M) av = *(const float4*)&A[(size_t)gm * K + k0 + aCol];
        else        av = make_float4(0.f, 0.f, 0.f, 0.f);
        As[aCol + 0][aRow] = av.x;
        As[aCol + 1][aRow] = av.y;
        As[aCol + 2][aRow] = av.z;
        As[aCol + 3][aRow] = av.w;

        float4 bv = *(const float4*)&B[(size_t)(k0 + bRow) * N + col0 + bCol];
        *(float4*)&Bs[bRow][bCol] = bv;
        __syncthreads();

#pragma unroll
        for (int kk = 0; kk < 16; ++kk) {
            float4 a = *(float4*)&As[kk][ty * 4];
            float4 b = *(float4*)&Bs[kk][tx * 4];
            unsigned long long b01, b23, a0, a1, a2, a3;
            PACK2(b01, b.x, b.y); PACK2(b23, b.z, b.w);
            PACK2(a0, a.x, a.x);  PACK2(a1, a.y, a.y);
            PACK2(a2, a.z, a.z);  PACK2(a3, a.w, a.w);
            FMA2(acc2[0][0], a0, b01); FMA2(acc2[0][1], a0, b23);
            FMA2(acc2[1][0], a1, b01); FMA2(acc2[1][1], a1, b23);
            FMA2(acc2[2][0], a2, b01); FMA2(acc2[2][1], a2, b23);
            FMA2(acc2[3][0], a3, b01); FMA2(acc2[3][1], a3, b23);
        }
        __syncthreads();
    }

#pragma unroll
    for (int i = 0; i < 4; ++i) {
        int m = row0 + ty * 4 + i;
        if (m < M) {
            float c0v, c1v, c2v, c3v;
            UNPACK2(c0v, c1v, acc2[i][0]);
            UNPACK2(c2v, c3v, acc2[i][1]);
            int n = col0 + tx * 4;
            Cout[(size_t)m * N + n + 0] = fmaxf(c0v + bias[n + 0], 0.f);
            Cout[(size_t)m * N + n + 1] = fmaxf(c1v + bias[n + 1], 0.f);
            Cout[(size_t)m * N + n + 2] = fmaxf(c2v + bias[n + 2], 0.f);
            Cout[(size_t)m * N + n + 3] = fmaxf(c3v + bias[n + 3], 0.f);
        }
    }
}

// ---------------- affinity dots, split-K=2, f32x2, REDG accumulate -------------
// g_aff[i][j] += partial dot(fn_i, fn_j); exp applied later in k_head_prop.
__global__ __launch_bounds__(256) void k_aff_part() {
    __shared__ float As[16][64];
    __shared__ float Bs[16][64];
    int tx = threadIdx.x, ty = threadIdx.y;
    int tid = ty * 16 + tx;
    int i0 = blockIdx.y * 64;
    int j0 = blockIdx.x * 64;
    int kbeg = blockIdx.z * (NCH / 2);
    int kend = kbeg + (NCH / 2);

    unsigned long long acc2[4][2];
#pragma unroll
    for (int i = 0; i < 4; ++i) { acc2[i][0] = 0ull; acc2[i][1] = 0ull; }

    int aRow = tid >> 2;
    int aCol = (tid & 3) * 4;

    for (int k0 = kbeg; k0 < kend; k0 += 16) {
        int gi = i0 + aRow;
        int gj = j0 + aRow;
        float4 av = (gi < NSEG) ? *(const float4*)&g_fn[(size_t)gi * NCH + k0 + aCol]
                                : make_float4(0.f, 0.f, 0.f, 0.f);
        float4 bv = (gj < NSEG) ? *(const float4*)&g_fn[(size_t)gj * NCH + k0 + aCol]
                                : make_float4(0.f, 0.f, 0.f, 0.f);
        As[aCol + 0][aRow] = av.x; As[aCol + 1][aRow] = av.y;
        As[aCol + 2][aRow] = av.z; As[aCol + 3][aRow] = av.w;
        Bs[aCol + 0][aRow] = bv.x; Bs[aCol + 1][aRow] = bv.y;
        Bs[aCol + 2][aRow] = bv.z; Bs[aCol + 3][aRow] = bv.w;
        __syncthreads();

#pragma unroll
        for (int kk = 0; kk < 16; ++kk) {
            float4 a = *(float4*)&As[kk][ty * 4];
            float4 b = *(float4*)&Bs[kk][tx * 4];
            unsigned long long b01, b23, a0, a1, a2, a3;
            PACK2(b01, b.x, b.y); PACK2(b23, b.z, b.w);
            PACK2(a0, a.x, a.x);  PACK2(a1, a.y, a.y);
            PACK2(a2, a.z, a.z);  PACK2(a3, a.w, a.w);
            FMA2(acc2[0][0], a0, b01); FMA2(acc2[0][1], a0, b23);
            FMA2(acc2[1][0], a1, b01); FMA2(acc2[1][1], a1, b23);
            FMA2(acc2[2][0], a2, b01); FMA2(acc2[2][1], a2, b23);
            FMA2(acc2[3][0], a3, b01); FMA2(acc2[3][1], a3, b23);
        }
        __syncthreads();
    }

#pragma unroll
    for (int i = 0; i < 4; ++i) {
        int gi = i0 + ty * 4 + i;
        if (gi < NSEG) {
            float c0v, c1v, c2v, c3v;
            UNPACK2(c0v, c1v, acc2[i][0]);
            UNPACK2(c2v, c3v, acc2[i][1]);
            int gj = j0 + tx * 4;
            float vals[4] = {c0v, c1v, c2v, c3v};
#pragma unroll
            for (int j = 0; j < 4; ++j) {
                if (gj + j < NSEG) {
                    float* dst = &g_aff[gi * NSEG + gj + j];
                    asm volatile("red.global.add.f32 [%0], %1;"
                                 :: "l"(dst), "f"(vals[j]) : "memory");
                }
            }
        }
    }
}

// ---------------- fused head (h3/softmax) + label propagation ------------------
__global__ __launch_bounds__(128) void k_head_prop(const float* __restrict__ W3,
                                                   const float* __restrict__ b3,
                                                   const float* __restrict__ Wc,
                                                   const float* __restrict__ bc,
                                                   float* __restrict__ out) {
    int i = blockIdx.x;
    int t = threadIdx.x;

    // ---- head: h3 = relu(h2@W3+b3); pred = softmax(h3@Wc+bc) ----
    {
        int n = t & 31;
        int ks = t >> 5;   // 4 k-slices of 256
        const float* h2r = g_h2 + (size_t)i * NH;
        float acc = 0.f;
        for (int kk = 0; kk < 256; ++kk) {
            int k = ks * 256 + kk;
            acc += h2r[k] * W3[k * 32 + n];
        }
        __shared__ float red[128];
        __shared__ float h3[32];
        red[t] = acc;
        __syncthreads();
        if (t < 32) {
            float v = red[t] + red[32 + t] + red[64 + t] + red[96 + t] + b3[t];
            h3[t] = fmaxf(v, 0.f);
        }
        __syncthreads();
        if (t == 0) {
            float l0 = bc[0], l1 = bc[1];
#pragma unroll
            for (int d = 0; d < 32; ++d) {
                l0 += h3[d] * Wc[d * 2 + 0];
                l1 += h3[d] * Wc[d * 2 + 1];
            }
            float m = fmaxf(l0, l1);
            float e0 = expf(l0 - m), e1 = expf(l1 - m);
            float inv = 1.f / (e0 + e1);
            out[i * 2 + 0] = e0 * inv;
            out[i * 2 + 1] = e1 * inv;
        }
        __syncthreads();
    }

    // ---- prop: masked argmax over aff row (aff = expf(-dot)) ----
    float bv = -INFINITY;
    int   bi = 0;
    for (int j = t; j < NSEG; j += 128) {
        if (g_lab[j] != 0) {
            float v = expf(-g_aff[i * NSEG + j]);
            if (v > bv) { bv = v; bi = j; }
        }
    }
    __shared__ float sv[128];
    __shared__ int   si[128];
    sv[t] = bv; si[t] = bi;
    __syncthreads();
    for (int o = 64; o; o >>= 1) {
        if (t < o) {
            float v2 = sv[t + o]; int i2 = si[t + o];
            if (v2 > sv[t] || (v2 == sv[t] && i2 < si[t])) { sv[t] = v2; si[t] = i2; }
        }
        __syncthreads();
    }
    if (t == 0) {
        int li = g_lab[i];
        int nl = (li == 0 && sv[0] >= 0.7f) ? g_lab[si[0]] : li;
        out[880 + i] = (float)nl;
    }
}

// ---------------- launcher -----------------------------------------------------
extern "C" void kernel_launch(void* const* d_in, const int* in_sizes, int n_in,
                              void* d_out, int out_size) {
    const float* fm = (const float*)d_in[0];
    const int*   sp = (const int*)d_in[1];
    const int*   y  = (const int*)d_in[2];
    const float* W1 = (const float*)d_in[3];
    const float* b1 = (const float*)d_in[4];
    const float* W2 = (const float*)d_in[5];
    const float* b2 = (const float*)d_in[6];
    const float* W3 = (const float*)d_in[7];
    const float* b3 = (const float*)d_in[8];
    const float* Wc = (const float*)d_in[9];
    const float* bc = (const float*)d_in[10];
    float* out = (float*)d_out;

    void *p_feat, *p_h1, *p_h2;
    cudaGetSymbolAddress(&p_feat, g_feat);
    cudaGetSymbolAddress(&p_h1, g_h1);
    cudaGetSymbolAddress(&p_h2, g_h2);

    k_zero<<<(NSEG * NCH + 255) / 256, 256>>>();
    k_hist<<<HW / 256, 256>>>(sp, y);
    k_seg<<<dim3(NCH / 4, 8), 256>>>(fm, sp);
    k_feat<<<NSEG, 256>>>();

    // h1 = relu(feat @ W1 + b1) : (440 x 2112) @ (2112 x 1024)
    k_gemm_relu<<<dim3(NH / 64, (NSEG + 63) / 64), dim3(16, 16)>>>(
        (const float*)p_feat, W1, b1, (float*)p_h1, NSEG, NH, NCH);
    // h2 = relu(h1 @ W2 + b2) : (440 x 1024) @ (1024 x 1024)
    k_gemm_relu<<<dim3(NH / 64, (NSEG + 63) / 64), dim3(16, 16)>>>(
        (const float*)p_h1, W2, b2, (float*)p_h2, NSEG, NH, NH);

    k_aff_part<<<dim3((NSEG + 63) / 64, (NSEG + 63) / 64, 2), dim3(16, 16)>>>();
    k_head_prop<<<NSEG, 128>>>(W3, b3, Wc, bc, out);
}